// round 4
// baseline (speedup 1.0000x reference)
#include <cuda_runtime.h>
#include <math.h>

#define B 8
#define N 1024
#define C 256
#define K 256
#define C2 512
#define SCALE 0.17677669529663687f   // (C/H)^-0.5 = 1/sqrt(32)

// Output layout: [new_X (8*256*256) | new_adj (8*256*256) | new_mask (8*256)]
#define OUT_ADJ_OFF  (B*K*C)
#define OUT_MASK_OFF (2*B*K*C)

// ---- scratch ----
__device__ int   d_idxg[B*K];
__device__ float d_gate[B*K];
__device__ float d_nm[B*K];

// ---------------------------------------------------------------------------
// Fused per-batch kernel. grid (B), 1024 threads, 64KB dynamic smem.
// Arithmetic for Xsum/ksum/u/scores bit-replicates the R2-passing kernels:
//   Xsum: 64 chunks x 16 sequential rows, then sequential 64-chunk sum.
//   ksum/u: single-accumulator sequential 256-term chains (256 threads).
//   scores: R2's k_scores inner expression + shuffle reduce, verbatim.
// ---------------------------------------------------------------------------
__global__ void __launch_bounds__(1024, 1)
k_fused(const float* __restrict__ X,
        const float* __restrict__ mask,
        const float* __restrict__ Wqkv,
        float* __restrict__ out) {
    int b = blockIdx.x, t = threadIdx.x;

    extern __shared__ float part64[];            // [64][256] chunk partials (64KB)
    __shared__ __align__(16) float xs[C];        // Xsum
    __shared__ __align__(16) float ks[C];        // ksum
    __shared__ __align__(16) float us[C];        // u vector
    __shared__ float scs[N];                     // scores
    __shared__ unsigned long long sk[N];         // sort keys
    __shared__ float red[32];
    __shared__ int s_ki;

    int c = t & 255, g = t >> 8;                 // column, chunk-group (4 groups)

    // ---- Pass 1: 16-row chunk partial sums, exactly R2's k_partial order.
    // Thread (g,c) handles chunks ch = g*16 .. g*16+15, column c.
    {
        #pragma unroll 1
        for (int chl = 0; chl < 16; chl++) {
            int ch = g * 16 + chl;
            const float* xp = X + ((size_t)b * N + (size_t)ch * 16) * C + c;
            float s = 0.f;
            #pragma unroll
            for (int r = 0; r < 16; r++) s += xp[(size_t)r * C];
            part64[ch * C + c] = s;
        }
    }
    // mask sum -> k_i (mask entries are 0/1: exact in any order)
    float ms = mask[b * N + t];
    #pragma unroll
    for (int o = 16; o; o >>= 1) ms += __shfl_xor_sync(0xffffffffu, ms, o);
    if ((t & 31) == 0) red[t >> 5] = ms;
    __syncthreads();

    // ---- Xsum: sequential 64-chunk sum (exactly R2's k_uvec order)
    if (t < 256) {
        float s = 0.f;
        #pragma unroll
        for (int ch = 0; ch < 64; ch++) s += part64[ch * C + t];
        xs[t] = s;
    }
    if (t == 0) {
        float s = 0.f;
        #pragma unroll
        for (int w = 0; w < 32; w++) s += red[w];
        s_ki = (int)ceilf(0.25f * s);
    }
    __syncthreads();

    // ---- ksum[t] = sum_c xs[c] * Wqkv[c, 256+t]  (sequential chain, R2 form)
    if (t < 256) {
        float ka = 0.f;
        for (int cc = 0; cc < C; cc++) ka += xs[cc] * Wqkv[(size_t)cc * C2 + C + t];
        ks[t] = ka;
    }
    __syncthreads();

    // ---- u[t] = sum_j Wqkv[t, j] * ksum[j]       (sequential chain, R2 form)
    if (t < 256) {
        const float* wrow = Wqkv + (size_t)t * C2;
        float ua = 0.f;
        for (int j = 0; j < C; j++) ua += wrow[j] * ks[j];
        us[t] = ua;
    }
    __syncthreads();

    // ---- Pass 2: scores, R2's k_scores inner arithmetic verbatim.
    // 32 warps, each handles 32 rows.
    {
        int warp = t >> 5, lane = t & 31;
        for (int rr = 0; rr < 32; rr++) {
            int n = warp * 32 + rr;
            const float4* xr = (const float4*)(X + ((size_t)b * N + n) * C);
            const float4* ur = (const float4*)us;
            float acc = 0.f;
            #pragma unroll
            for (int it = 0; it < 2; it++) {
                float4 xv = xr[lane + it * 32];
                float4 uv = ur[lane + it * 32];
                acc += xv.x * uv.x + xv.y * uv.y + xv.z * uv.z + xv.w * uv.w;
            }
            #pragma unroll
            for (int o = 16; o; o >>= 1) acc += __shfl_xor_sync(0xffffffffu, acc, o);
            if (lane == 0) {
                float m = mask[b * N + n];
                scs[n] = (m > 0.f) ? SCALE * acc : -1e9f;
            }
        }
    }
    __syncthreads();

    // ---- Top-k: hybrid bitonic (proven in R2). Ascending u64 key ==
    // descending score, ascending index tie-break (matches jax.lax.top_k).
    unsigned long long v;
    {
        float f = scs[t];
        unsigned u = __float_as_uint(f);
        u = (u & 0x80000000u) ? ~u : (u | 0x80000000u);
        v = ((unsigned long long)(~u) << 32) | (unsigned)t;
    }
    #pragma unroll
    for (unsigned k = 2; k <= 1024; k <<= 1) {
        bool dir_up = ((t & k) == 0);
        for (unsigned j = k >> 1; j >= 32; j >>= 1) {
            sk[t] = v;
            __syncthreads();
            unsigned long long w = sk[t ^ j];
            bool lower = ((t & j) == 0);
            bool takeMin = (lower == dir_up);
            v = takeMin ? (v < w ? v : w) : (v > w ? v : w);
            __syncthreads();
        }
        unsigned jstart = (k >> 1) < 16u ? (k >> 1) : 16u;
        for (unsigned j = jstart; j >= 1; j >>= 1) {
            unsigned long long w = __shfl_xor_sync(0xffffffffu, v, j);
            bool lower = ((t & j) == 0);
            bool takeMin = (lower == dir_up);
            v = takeMin ? (v < w ? v : w) : (v > w ? v : w);
        }
    }
    sk[t] = v;
    __syncthreads();

    if (t < K) {
        unsigned long long key = sk[t];
        int n = (int)(unsigned)key;
        unsigned uh = ~(unsigned)(key >> 32);           // recover score bits
        unsigned orig = (uh & 0x80000000u) ? (uh & 0x7fffffffu) : ~uh;
        float val = __uint_as_float(orig);
        float nm = (t < s_ki) ? 1.f : 0.f;
        d_idxg[b * K + t] = n;
        d_gate[b * K + t] = tanhf(val) * nm;
        d_nm[b * K + t]   = nm;
        out[OUT_MASK_OFF + b * K + t] = nm;
    }
}

// ---------------------------------------------------------------------------
// Gather kernel. grid (K, B), 256 threads.
//   new_X[b,i,:]   = X[b, idx[i], :] * gate[i]          (coalesced)
//   new_adj[b,i,j] = adj[b, idx[i], idx[j]] * nm[i]*nm[j]
// adj row staged in shared via coalesced float4 loads, then LDS gather.
// ---------------------------------------------------------------------------
__global__ void k_gather(const float* __restrict__ X,
                         const float* __restrict__ adj,
                         float* __restrict__ out) {
    int b = blockIdx.y, i = blockIdx.x, t = threadIdx.x;
    __shared__ int   sidx[K];
    __shared__ float snm[K];
    __shared__ __align__(16) float srow[N];
    sidx[t] = d_idxg[b * K + t];
    snm[t]  = d_nm[b * K + t];
    __syncthreads();

    int ri = sidx[i];
    float nmi = snm[i];
    float gte = d_gate[b * K + i];

    // stage full adj row (4KB) coalesced
    {
        const float4* row4 = (const float4*)(adj + (size_t)b * N * N + (size_t)ri * N);
        ((float4*)srow)[t] = row4[t];
    }
    // new_X row (coalesced read+write), overlap with staging
    out[((size_t)b * K + i) * C + t] = X[((size_t)b * N + ri) * C + t] * gte;
    __syncthreads();

    out[OUT_ADJ_OFF + ((size_t)b * K + i) * K + t] = srow[sidx[t]] * nmi * snm[t];
}

// ---------------------------------------------------------------------------
extern "C" void kernel_launch(void* const* d_in, const int* in_sizes, int n_in,
                              void* d_out, int out_size) {
    const float* X    = (const float*)d_in[0];
    const float* adj  = (const float*)d_in[1];
    const float* mask = (const float*)d_in[2];
    const float* Wqkv = (const float*)d_in[3];
    float* out = (float*)d_out;

    cudaFuncSetAttribute(k_fused, cudaFuncAttributeMaxDynamicSharedMemorySize, 65536);
    k_fused<<<B, 1024, 65536>>>(X, mask, Wqkv, out);
    k_gather<<<dim3(K, B), 256>>>(X, adj, out);
}